// round 16
// baseline (speedup 1.0000x reference)
#include <cuda_runtime.h>
#include <cstdint>

#define BB 32
#define TT 4096
#define HH 256
#define NTHREADS 256
#define NWARPS 8
#define OCC 3
#define GRID 444                 // 148 SMs x 3 CTAs = one wave
#define NUNITS 16384             // 131072 rows / 8 rows-per-unit
#define PF 4                     // rows in flight per warp

#define ALPHA 0.1f
#define LOG2_09 (-0.15200309344504997f)
#define MASK_PENALTY 1000000.0f

// per (CTA, seg, warp): 444 * 2 * 8 floats, 16B aligned for float4 fold
__device__ __align__(16) float g_p2[GRID * 16];
__device__ unsigned int g_done = 0;

__global__ __launch_bounds__(NTHREADS, OCC)
void pool_static(const float* __restrict__ x,
                 const int*   __restrict__ mask,
                 const float* __restrict__ weight_ema,
                 const float* __restrict__ weight_mean,
                 const float* __restrict__ W,
                 const float* __restrict__ bias,
                 float*       __restrict__ out)
{
    const int tid  = threadIdx.x;
    const int wid  = tid >> 5;
    const int lane = tid & 31;
    const int c    = blockIdx.x;

    __shared__ bool s_is_last;

    // Per-lane W slices (each lane owns 8 of the 256 W values, split halves)
    const float4* W4 = reinterpret_cast<const float4*>(W);
    const float4 wa = __ldg(W4 + lane);        // W[lane*4 .. +3]
    const float4 wb = __ldg(W4 + 32 + lane);   // W[128 + lane*4 .. +3]

    float wsum = wa.x + wa.y + wa.z + wa.w + wb.x + wb.y + wb.z + wb.w;
    #pragma unroll
    for (int off = 16; off > 0; off >>= 1)
        wsum += __shfl_xor_sync(0xffffffffu, wsum, off);

    const float we        = __ldg(weight_ema);
    const float wm_over_T = __ldg(weight_mean) * (1.0f / (float)TT);
    const float cs        = we * ALPHA;
    const float penw      = MASK_PENALTY * wsum;

    // Static contiguous range: units of 8 rows, proportional split.
    const unsigned u0 = ((unsigned)c       * NUNITS) / GRID;
    const unsigned u1 = ((unsigned)(c + 1) * NUNITS) / GRID;
    const int nk = (int)(u1 - u0);                 // 36 or 37 steps
    const int b0 = (int)(u0 >> 9);                 // 512 units per batch
    const int kc = (b0 + 1) * 512 - (int)u0;       // batch-crossing step (may be >= nk)
    const int r0 = (int)u0 * 8 + wid;              // this warp's first row

    const float4* x4 = reinterpret_cast<const float4*>(x);

    float acc = 0.0f, pen = 0.0f;
    bool crossed = false;

    // rotating PF=4 prefetch over the warp's whole row sequence (stride 8 rows)
    float4 Abuf[PF], Cbuf[PF];
    #pragma unroll
    for (int k = 0; k < PF; k++) {
        if (k < nk) {
            const float4* p = x4 + (size_t)(r0 + 8 * k) * (HH / 4);
            Abuf[k] = __ldg(p + lane);
            Cbuf[k] = __ldg(p + 32 + lane);
        }
    }

    for (int k = 0; k < nk; k++) {
        if (k == kc) {
            // flush segment 0 at the batch boundary (warp-uniform condition)
            float v = acc;
            #pragma unroll
            for (int off = 16; off > 0; off >>= 1)
                v += __shfl_xor_sync(0xffffffffu, v, off);
            if (lane == 0) g_p2[c * 16 + wid] = v - pen * penw;
            acc = 0.0f; pen = 0.0f; crossed = true;
        }

        const int s = k & (PF - 1);
        float4 a  = Abuf[s];
        float4 c2 = Cbuf[s];
        const int kn = k + PF;
        if (kn < nk) {
            const float4* p = x4 + (size_t)(r0 + 8 * kn) * (HH / 4);
            Abuf[s] = __ldg(p + lane);
            Cbuf[s] = __ldg(p + 32 + lane);
        }

        const int r = r0 + 8 * k;          // flattened row = b*TT + t
        const int t = r & (TT - 1);
        float wt = exp2f((float)(TT - 1 - t) * LOG2_09);
        float cf = (t == 0) ? fmaf(we, wt, wm_over_T)
                            : fmaf(cs, wt, wm_over_T);

        float p0 = a.x * wa.x;
        float p1 = a.y * wa.y;
        p0 = fmaf(a.z,  wa.z, p0);
        p1 = fmaf(a.w,  wa.w, p1);
        p0 = fmaf(c2.x, wb.x, p0);
        p1 = fmaf(c2.y, wb.y, p1);
        p0 = fmaf(c2.z, wb.z, p0);
        p1 = fmaf(c2.w, wb.w, p1);

        acc = fmaf(cf, p0 + p1, acc);
        if (__ldg(mask + r) == 0) pen += cf;    // warp-uniform scalar
    }

    // final flush: seg1 if crossed, else seg0 (and zero seg1)
    {
        float v = acc;
        #pragma unroll
        for (int off = 16; off > 0; off >>= 1)
            v += __shfl_xor_sync(0xffffffffu, v, off);
        const int seg = crossed ? 1 : 0;
        if (lane == 0) {
            g_p2[c * 16 + seg * 8 + wid] = v - pen * penw;
            if (!crossed) g_p2[c * 16 + 8 + wid] = 0.0f;
        }
    }

    // ---- completion ----
    __threadfence();
    __syncthreads();
    if (tid == 0) {
        unsigned ticket = atomicAdd(&g_done, 1u);
        s_is_last = (ticket == (unsigned)(GRID - 1));
    }
    __syncthreads();

    // ---- last CTA: fold 444*16 partials -> 32 outputs ----
    // seg0 of CTA cc belongs to batch b0(cc); seg1 to b0(cc)+1 (zero if unused).
    if (s_is_last) {
        const float bv = __ldg(bias);
        const float4* p4all = reinterpret_cast<const float4*>(g_p2);
        #pragma unroll
        for (int kb = 0; kb < BB / NWARPS; kb++) {
            const int bb = wid * (BB / NWARPS) + kb;
            int cmin = (bb > 0) ? ((bb - 1) * GRID) / BB - 2 : 0;
            if (cmin < 0) cmin = 0;
            int cmax = ((bb + 1) * GRID) / BB + 2;
            if (cmax > GRID - 1) cmax = GRID - 1;

            float v = 0.0f;
            for (int cc = cmin + lane; cc <= cmax; cc += 32) {
                const unsigned uu0 = ((unsigned)cc * NUNITS) / GRID;
                const int bb0 = (int)(uu0 >> 9);
                const float4* p4 = p4all + cc * 4;
                if (bb0 == bb) {           // seg0 -> batch bb
                    float4 q = __ldcg(p4), q2 = __ldcg(p4 + 1);
                    v += q.x + q.y + q.z + q.w + q2.x + q2.y + q2.z + q2.w;
                }
                if (bb0 == bb - 1) {       // seg1 -> batch bb
                    float4 q = __ldcg(p4 + 2), q2 = __ldcg(p4 + 3);
                    v += q.x + q.y + q.z + q.w + q2.x + q2.y + q2.z + q2.w;
                }
            }
            #pragma unroll
            for (int off = 16; off > 0; off >>= 1)
                v += __shfl_xor_sync(0xffffffffu, v, off);
            if (lane == 0) out[bb] = v + bv;
        }
        if (tid == 0) g_done = 0;          // reset for next graph replay
    }
}

extern "C" void kernel_launch(void* const* d_in, const int* in_sizes, int n_in,
                              void* d_out, int out_size)
{
    const float* x    = (const float*)d_in[0];
    const int*   mask = (const int*)d_in[1];
    const float* we   = (const float*)d_in[2];
    const float* wm   = (const float*)d_in[3];
    const float* W    = (const float*)d_in[4];
    const float* bias = (const float*)d_in[5];
    float* out = (float*)d_out;

    pool_static<<<GRID, NTHREADS>>>(x, mask, we, wm, W, bias, out);
}

// round 17
// speedup vs baseline: 1.4065x; 1.4065x over previous
#include <cuda_runtime.h>
#include <cstdint>

#define BB 32
#define TT 4096
#define HH 256
#define TILE_ROWS 64
#define CHUNKS (TT / TILE_ROWS)             // 64 tiles per batch
#define NTILES (BB * CHUNKS)                // 2048 tiles
#define NTHREADS 256
#define NWARPS 8
#define ROWS_PER_WARP (TILE_ROWS / NWARPS)  // 8
#define OCC 3
#define GRID (148 * OCC)                    // 444: one wave at occ=3
#define PF 4                                // prefetch depth (rows in flight)

#define ALPHA 0.1f
#define LOG2_09 (-0.15200309344504997f)     // log2(0.9)
#define MASK_PENALTY 1000000.0f

__device__ float g_partial[NTILES];
__device__ unsigned int g_work = 0;
__device__ unsigned int g_done = 0;

__global__ __launch_bounds__(NTHREADS, OCC)
void pool_persistent(const float* __restrict__ x,
                     const int*   __restrict__ mask,
                     const float* __restrict__ weight_ema,
                     const float* __restrict__ weight_mean,
                     const float* __restrict__ W,
                     const float* __restrict__ bias,
                     float*       __restrict__ out)
{
    const int tid  = threadIdx.x;
    const int wid  = tid >> 5;
    const int lane = tid & 31;

    __shared__ float s_warp_acc[NWARPS];
    __shared__ int   s_tile;
    __shared__ bool  s_is_last;

    // Per-lane W slices (each lane owns 8 of the 256 W values)
    const float4* W4 = reinterpret_cast<const float4*>(W);
    const float4 wa = __ldg(W4 + lane);        // W[lane*4 .. +3]
    const float4 wb = __ldg(W4 + 32 + lane);   // W[128 + lane*4 .. +3]

    // Warp-wide Wsum (identical in every warp -> deterministic)
    float wsum = wa.x + wa.y + wa.z + wa.w + wb.x + wb.y + wb.z + wb.w;
    #pragma unroll
    for (int off = 16; off > 0; off >>= 1)
        wsum += __shfl_xor_sync(0xffffffffu, wsum, off);

    const float we        = __ldg(weight_ema);
    const float wm_over_T = __ldg(weight_mean) * (1.0f / (float)TT);
    const float cs        = we * ALPHA;     // coeff on 0.9^(T-1-t), t>0
    const float penw      = MASK_PENALTY * wsum;

    // ---- dynamic work loop: one 64-row tile per ticket ----
    while (true) {
        if (tid == 0) s_tile = (int)atomicAdd(&g_work, 1u);
        __syncthreads();
        const int tile = s_tile;
        if (tile >= NTILES) break;

        const int b     = tile / CHUNKS;
        const int chunk = tile % CHUNKS;
        const int t0    = chunk * TILE_ROWS + wid * ROWS_PER_WARP;

        const float4* xbase = reinterpret_cast<const float4*>(x) +
                              (size_t)(b * TT + t0) * (HH / 4);
        const int* mrow = mask + b * TT + t0;

        // mask bits for this warp's 8 rows (one broadcast load + ballot)
        int mv = (lane < ROWS_PER_WARP) ? __ldg(mrow + lane) : 1;
        const unsigned penbits =
            __ballot_sync(0xffffffffu, (lane < ROWS_PER_WARP) && (mv == 0));

        // EMA weight start for this warp's first row
        float wt0 = exp2f((float)(TT - 1 - t0) * LOG2_09);

        float acc     = 0.0f;
        float pen_sum = 0.0f;

        // rotating prefetch: PF rows (4 KB/warp) in flight
        float4 Abuf[PF], Cbuf[PF];
        #pragma unroll
        for (int k = 0; k < PF; k++) {
            const float4* p = xbase + (size_t)k * (HH / 4);
            Abuf[k] = __ldg(p + lane);
            Cbuf[k] = __ldg(p + 32 + lane);
        }

        float wt = wt0;
        #pragma unroll
        for (int i = 0; i < ROWS_PER_WARP; i++) {
            const int s = i & (PF - 1);
            float4 a  = Abuf[s];
            float4 c2 = Cbuf[s];
            if (i + PF < ROWS_PER_WARP) {
                const float4* p = xbase + (size_t)(i + PF) * (HH / 4);
                Abuf[s] = __ldg(p + lane);
                Cbuf[s] = __ldg(p + 32 + lane);
            }

            // c = we * w_ema[t] + wm/T  (row t=0 lacks the alpha factor)
            float c;
            if (tile == 0 && wid == 0 && i == 0) c = fmaf(we, wt, wm_over_T);
            else                                 c = fmaf(cs, wt, wm_over_T);
            wt *= 1.1111111111111112f;   // 1/0.9 recurrence

            float p0 = a.x * wa.x;
            float p1 = a.y * wa.y;
            p0 = fmaf(a.z,  wa.z, p0);
            p1 = fmaf(a.w,  wa.w, p1);
            p0 = fmaf(c2.x, wb.x, p0);
            p1 = fmaf(c2.y, wb.y, p1);
            p0 = fmaf(c2.z, wb.z, p0);
            p1 = fmaf(c2.w, wb.w, p1);

            acc = fmaf(c, p0 + p1, acc);
            if ((penbits >> i) & 1u) pen_sum += c;
        }

        // one butterfly per warp (fixed order -> deterministic)
        #pragma unroll
        for (int off = 16; off > 0; off >>= 1)
            acc += __shfl_xor_sync(0xffffffffu, acc, off);

        if (lane == 0) s_warp_acc[wid] = acc - pen_sum * penw;
        __syncthreads();

        if (tid == 0) {
            float v = 0.0f;
            #pragma unroll
            for (int w = 0; w < NWARPS; w++) v += s_warp_acc[w];  // fixed order
            g_partial[tile] = v;
        }
        // next iteration's __syncthreads() (after s_tile write) orders reuse
    }

    // ---- completion + final fold by last CTA ----
    if (tid == 0) {
        __threadfence();
        unsigned ticket = atomicAdd(&g_done, 1u);
        s_is_last = (ticket == (unsigned)(GRID - 1));
    }
    __syncthreads();

    if (s_is_last) {
        const float bv = __ldg(bias);
        // 8 warps x 4 batches each; each batch folds 64 chunk partials.
        #pragma unroll
        for (int k = 0; k < BB / NWARPS; k++) {
            const int bb = wid * (BB / NWARPS) + k;
            float v = __ldcg(&g_partial[bb * CHUNKS + lane])
                    + __ldcg(&g_partial[bb * CHUNKS + 32 + lane]);
            #pragma unroll
            for (int off = 16; off > 0; off >>= 1)
                v += __shfl_xor_sync(0xffffffffu, v, off);
            if (lane == 0) out[bb] = v + bv;
        }
        if (tid == 0) { g_work = 0; g_done = 0; }  // reset for next replay
    }
}

extern "C" void kernel_launch(void* const* d_in, const int* in_sizes, int n_in,
                              void* d_out, int out_size)
{
    const float* x    = (const float*)d_in[0];
    const int*   mask = (const int*)d_in[1];
    const float* we   = (const float*)d_in[2];
    const float* wm   = (const float*)d_in[3];
    const float* W    = (const float*)d_in[4];
    const float* bias = (const float*)d_in[5];
    float* out = (float*)d_out;

    pool_persistent<<<GRID, NTHREADS>>>(x, mask, we, wm, W, bias, out);
}